// round 3
// baseline (speedup 1.0000x reference)
#include <cuda_runtime.h>
#include <math.h>

// ---------------------------------------------------------------------------
// Problem constants
// ---------------------------------------------------------------------------
#define BB   64          // batch
#define SS   32          // seq
#define HH   1024        // hidden
#define RR   256         // GRU hidden
#define DEPTH 9
#define LEAVES 512       // 2^DEPTH
#define MAXM (BB*LEAVES) // 32768 max rows

#define SELU_SCALE 1.0507009873554805f
#define SELU_ALPHA 1.6732632423543772f

__device__ __forceinline__ float seluf(float v) {
    return v > 0.f ? SELU_SCALE * v : SELU_SCALE * SELU_ALPHA * expm1f(v);
}
__device__ __forceinline__ float sigmoidf_(float v) {
    return 1.f / (1.f + __expf(-v));
}

// ---------------------------------------------------------------------------
// Scratch (device globals; no allocation allowed)
// ---------------------------------------------------------------------------
__device__ float g_xcA[(size_t)MAXM * HH];
__device__ float g_xcB[(size_t)MAXM * HH];
__device__ float g_hcA[(size_t)MAXM * RR];
__device__ float g_hcB[(size_t)MAXM * RR];
__device__ float g_dA[MAXM];
__device__ float g_dB[MAXM];
__device__ float g_gi[(size_t)MAXM * 3 * RR];
__device__ float g_gh[(size_t)MAXM * 3 * RR];
__device__ float g_xh[(size_t)MAXM * (HH + RR)];
__device__ float g_lr[(size_t)(MAXM/2) * 2 * HH];
__device__ float g_sx[(size_t)BB * SS * HH];
__device__ float g_y [(size_t)BB * SS * HH];

// ---------------------------------------------------------------------------
// SGEMM: C[M,N] = epi(A[M,K] @ W[N,K]^T + bias[N])
//   EPI 0: bias only
//   EPI 1: selu(bias add)
//   EPI 2: child residual: C[r] = P[r>>1] - selu(v)   (N must be 1024)
// Requires N % 128 == 0, K % 16 == 0. M is guarded.
// ---------------------------------------------------------------------------
template<int EPI>
__global__ __launch_bounds__(256)
void sgemm(const float* __restrict__ A, const float* __restrict__ W,
           const float* __restrict__ bias, float* __restrict__ C,
           int M, int N, int K, const float* __restrict__ P)
{
    __shared__ float As[16][128];
    __shared__ float Bs[16][128];
    const int tid = threadIdx.x;
    const int tx = tid & 15, ty = tid >> 4;
    const int row0 = blockIdx.y * 128;
    const int col0 = blockIdx.x * 128;

    float acc[8][8];
    #pragma unroll
    for (int i = 0; i < 8; i++)
        #pragma unroll
        for (int j = 0; j < 8; j++) acc[i][j] = 0.f;

    for (int k0 = 0; k0 < K; k0 += 16) {
        #pragma unroll
        for (int i = 0; i < 2; i++) {
            int f  = i * 256 + tid;
            int r  = f >> 2;
            int c4 = (f & 3) * 4;
            float4 v = make_float4(0.f, 0.f, 0.f, 0.f);
            int gr = row0 + r;
            if (gr < M) v = *(const float4*)(A + (size_t)gr * K + k0 + c4);
            As[c4+0][r] = v.x; As[c4+1][r] = v.y; As[c4+2][r] = v.z; As[c4+3][r] = v.w;
            int gn = col0 + r;  // N tiles always full
            float4 w = *(const float4*)(W + (size_t)gn * K + k0 + c4);
            Bs[c4+0][r] = w.x; Bs[c4+1][r] = w.y; Bs[c4+2][r] = w.z; Bs[c4+3][r] = w.w;
        }
        __syncthreads();
        #pragma unroll
        for (int kk = 0; kk < 16; kk++) {
            float4 a0 = *(const float4*)&As[kk][ty * 8];
            float4 a1 = *(const float4*)&As[kk][ty * 8 + 4];
            float4 b0 = *(const float4*)&Bs[kk][tx * 8];
            float4 b1 = *(const float4*)&Bs[kk][tx * 8 + 4];
            float a[8] = {a0.x,a0.y,a0.z,a0.w,a1.x,a1.y,a1.z,a1.w};
            float b[8] = {b0.x,b0.y,b0.z,b0.w,b1.x,b1.y,b1.z,b1.w};
            #pragma unroll
            for (int i = 0; i < 8; i++)
                #pragma unroll
                for (int j = 0; j < 8; j++)
                    acc[i][j] = fmaf(a[i], b[j], acc[i][j]);
        }
        __syncthreads();
    }

    #pragma unroll
    for (int i = 0; i < 8; i++) {
        int r = row0 + ty * 8 + i;
        if (r >= M) continue;
        #pragma unroll
        for (int j = 0; j < 8; j++) {
            int c = col0 + tx * 8 + j;
            float v = acc[i][j] + bias[c];
            if (EPI == 1) v = seluf(v);
            if (EPI == 2) v = P[(size_t)(r >> 1) * HH + c] - seluf(v);
            C[(size_t)r * N + c] = v;
        }
    }
}

// ---------------------------------------------------------------------------
// Elementwise kernels
// ---------------------------------------------------------------------------
__global__ void selu_kernel(const float* __restrict__ in, float* __restrict__ out, int n) {
    int i = blockIdx.x * blockDim.x + threadIdx.x;
    if (i < n) out[i] = seluf(in[i]);
}

__global__ void mean_kernel(const float* __restrict__ y, float* __restrict__ xc) {
    int i = blockIdx.x * blockDim.x + threadIdx.x;   // over B*H
    if (i >= BB * HH) return;
    int b = i / HH, h = i - b * HH;
    float s = 0.f;
    #pragma unroll 8
    for (int t = 0; t < SS; t++) s += y[((size_t)(b * SS + t)) * HH + h];
    xc[i] = s * (1.f / SS);
}

__global__ void zero_kernel(float* p, int n) {
    int i = blockIdx.x * blockDim.x + threadIdx.x;
    if (i < n) p[i] = 0.f;
}

__global__ void gru_kernel(const float* __restrict__ gi, const float* __restrict__ gh,
                           float* __restrict__ hc, int M) {
    int i = blockIdx.x * blockDim.x + threadIdx.x;
    if (i >= M * RR) return;
    int m = i >> 8, j = i & (RR - 1);
    size_t o = (size_t)m * (3 * RR) + j;
    float ir = gi[o], iz = gi[o + RR], inn = gi[o + 2 * RR];
    float hr = gh[o], hz = gh[o + RR], hn  = gh[o + 2 * RR];
    float r = sigmoidf_(ir + hr);
    float z = sigmoidf_(iz + hz);
    float n = tanhf(inn + r * hn);
    size_t ho = (size_t)m * RR + j;
    hc[ho] = (1.f - z) * n + z * hc[ho];
}

__global__ void concat_kernel(const float* __restrict__ xc, const float* __restrict__ hc,
                              float* __restrict__ xh, int M) {
    int i = blockIdx.x * blockDim.x + threadIdx.x;   // float4 over M*320
    if (i >= M * 320) return;
    int m = i / 320, k = i - m * 320;
    float4 v = (k < 256) ? ((const float4*)xc)[(size_t)m * 256 + k]
                         : ((const float4*)hc)[(size_t)m * 64 + (k - 256)];
    ((float4*)xh)[(size_t)m * 320 + k] = v;
}

__global__ void hb_kernel(const float* __restrict__ xh, const float* __restrict__ Whb,
                          const float* __restrict__ bhb, const float* __restrict__ dIn,
                          float* __restrict__ dOut, int M) {
    int w = (blockIdx.x * blockDim.x + threadIdx.x) >> 5;
    int lane = threadIdx.x & 31;
    if (w >= M) return;
    const float4* row = (const float4*)(xh + (size_t)w * (HH + RR));
    const float4* wv  = (const float4*)Whb;
    float s = 0.f;
    #pragma unroll 5
    for (int i = lane; i < 320; i += 32) {
        float4 a = row[i], b = wv[i];
        s += a.x * b.x + a.y * b.y + a.z * b.z + a.w * b.w;
    }
    #pragma unroll
    for (int o = 16; o; o >>= 1) s += __shfl_xor_sync(0xffffffffu, s, o);
    if (lane == 0) dOut[w] = dIn[w] + sigmoidf_(s + bhb[0]);
}

__global__ void repeat_kernel(const float* __restrict__ hcIn, const float* __restrict__ dIn,
                              float* __restrict__ hcOut, float* __restrict__ dOut, int M2) {
    int i = blockIdx.x * blockDim.x + threadIdx.x;   // float4 over M2*64
    if (i >= M2 * 64) return;
    int m = i >> 6, j = i & 63;
    ((float4*)hcOut)[(size_t)m * 64 + j] = ((const float4*)hcIn)[(size_t)(m >> 1) * 64 + j];
    if (j == 0) dOut[m] = dIn[m >> 1];
}

__global__ void out_kernel(const float* __restrict__ xc, const float* __restrict__ dep,
                           float* __restrict__ out) {
    int i = blockIdx.x * blockDim.x + threadIdx.x;   // over 32768*1025
    if (i >= MAXM * (HH + 1)) return;
    int m = i / (HH + 1), k = i - m * (HH + 1);
    out[i] = (k < HH) ? xc[(size_t)m * HH + k] : dep[m];
}

// ---------------------------------------------------------------------------
// Host driver (graph-capturable: only kernel launches)
// ---------------------------------------------------------------------------
static inline int cdiv(int a, int b) { return (a + b - 1) / b; }

extern "C" void kernel_launch(void* const* d_in, const int* in_sizes, int n_in,
                              void* d_out, int out_size)
{
    const float* x        = (const float*)d_in[0];
    const float* W_hidden = (const float*)d_in[1];
    const float* b_hidden = (const float*)d_in[2];
    const float* W_hb     = (const float*)d_in[3];
    const float* b_hb     = (const float*)d_in[4];
    const float* W_branch = (const float*)d_in[5];
    const float* b_branch = (const float*)d_in[6];
    const float* W_ih     = (const float*)d_in[7];
    const float* W_hh     = (const float*)d_in[8];
    const float* b_ih     = (const float*)d_in[9];
    const float* b_hh     = (const float*)d_in[10];

    float *xcA, *xcB, *hcA, *hcB, *dA, *dB, *gi, *gh, *xh, *lr, *sx, *y;
    cudaGetSymbolAddress((void**)&xcA, g_xcA);
    cudaGetSymbolAddress((void**)&xcB, g_xcB);
    cudaGetSymbolAddress((void**)&hcA, g_hcA);
    cudaGetSymbolAddress((void**)&hcB, g_hcB);
    cudaGetSymbolAddress((void**)&dA,  g_dA);
    cudaGetSymbolAddress((void**)&dB,  g_dB);
    cudaGetSymbolAddress((void**)&gi,  g_gi);
    cudaGetSymbolAddress((void**)&gh,  g_gh);
    cudaGetSymbolAddress((void**)&xh,  g_xh);
    cudaGetSymbolAddress((void**)&lr,  g_lr);
    cudaGetSymbolAddress((void**)&sx,  g_sx);
    cudaGetSymbolAddress((void**)&y,   g_y);

    const int nsx = BB * SS * HH;  // 2,097,152

    // ---- root: xc0 = mean_s selu(selu(x) @ W_hidden^T + b_hidden) ----
    selu_kernel<<<cdiv(nsx, 256), 256>>>(x, sx, nsx);
    sgemm<1><<<dim3(HH / 128, cdiv(BB * SS, 128)), 256>>>(
        sx, W_hidden, b_hidden, y, BB * SS, HH, HH, nullptr);
    mean_kernel<<<cdiv(BB * HH, 256), 256>>>(y, xcA);
    zero_kernel<<<cdiv(BB * RR, 256), 256>>>(hcA, BB * RR);
    zero_kernel<<<1, 64>>>(dA, BB);

    // ---- levels 0 .. DEPTH-1 ----
    for (int d = 0; d < DEPTH; d++) {
        int M  = BB << d;        // parents
        int M2 = M << 1;         // children

        // GRU gates
        sgemm<0><<<dim3(768 / 128, cdiv(M, 128)), 256>>>(
            xcA, W_ih, b_ih, gi, M, 768, HH, nullptr);
        sgemm<0><<<dim3(768 / 128, cdiv(M, 128)), 256>>>(
            hcA, W_hh, b_hh, gh, M, 768, RR, nullptr);
        gru_kernel<<<cdiv(M * RR, 256), 256>>>(gi, gh, hcA, M);

        // xh = [xc | hc]; depth += sigmoid(xh . W_hb + b_hb)
        concat_kernel<<<cdiv(M * 320, 256), 256>>>(xcA, hcA, xh, M);
        hb_kernel<<<cdiv(M * 32, 256), 256>>>(xh, W_hb, b_hb, dA, dA, M);

        // lr = selu(xh @ W_branch^T + b_branch)   [M, 2048]
        sgemm<1><<<dim3(2 * HH / 128, cdiv(M, 128)), 256>>>(
            xh, W_branch, b_branch, lr, M, 2 * HH, HH + RR, nullptr);

        // children: xcB[r] = xcA[r>>1] - selu(lr_view[r] @ W_hidden^T + b_hidden)
        sgemm<2><<<dim3(HH / 128, cdiv(M2, 128)), 256>>>(
            lr, W_hidden, b_hidden, xcB, M2, HH, HH, xcA);

        repeat_kernel<<<cdiv(M2 * 64, 256), 256>>>(hcA, dA, hcB, dB, M2);

        float* t;
        t = xcA; xcA = xcB; xcB = t;
        t = hcA; hcA = hcB; hcB = t;
        t = dA;  dA  = dB;  dB  = t;
    }

    // ---- leaf step (M = 32768) ----
    {
        int M = MAXM;
        sgemm<0><<<dim3(768 / 128, cdiv(M, 128)), 256>>>(
            xcA, W_ih, b_ih, gi, M, 768, HH, nullptr);
        sgemm<0><<<dim3(768 / 128, cdiv(M, 128)), 256>>>(
            hcA, W_hh, b_hh, gh, M, 768, RR, nullptr);
        gru_kernel<<<cdiv(M * RR, 256), 256>>>(gi, gh, hcA, M);
        concat_kernel<<<cdiv(M * 320, 256), 256>>>(xcA, hcA, xh, M);
        hb_kernel<<<cdiv(M * 32, 256), 256>>>(xh, W_hb, b_hb, dA, dA, M);
        out_kernel<<<cdiv(M * (HH + 1), 256), 256>>>(xcA, dA, (float*)d_out);
    }
}

// round 4
// speedup vs baseline: 2.2176x; 2.2176x over previous
#include <cuda_runtime.h>
#include <cuda_bf16.h>
#include <math.h>
#include <stdint.h>

// ---------------------------------------------------------------------------
// Problem constants
// ---------------------------------------------------------------------------
#define BB   64          // batch
#define SS   32          // seq
#define HH   1024        // hidden
#define RR   256         // GRU hidden
#define DEPTH 9
#define LEAVES 512
#define MAXM (BB*LEAVES) // 32768 max rows

#define SELU_SCALE 1.0507009873554805f
#define SELU_ALPHA 1.6732632423543772f

typedef __nv_bfloat16 bf16;

__device__ __forceinline__ float seluf(float v) {
    return v > 0.f ? SELU_SCALE * v : SELU_SCALE * SELU_ALPHA * expm1f(v);
}
__device__ __forceinline__ float sigmoidf_(float v) {
    return 1.f / (1.f + __expf(-v));
}
__device__ __forceinline__ void split1(float v, bf16& h, bf16& l) {
    h = __float2bfloat16(v);
    l = __float2bfloat16(v - __bfloat162float(h));
}

// ---------------------------------------------------------------------------
// Scratch (device globals; allocation is forbidden)
// ---------------------------------------------------------------------------
// fp32 state
__device__ float g_xcA[(size_t)MAXM * HH];
__device__ float g_xcB[(size_t)MAXM * HH];
__device__ float g_hcA[(size_t)MAXM * RR];
__device__ float g_hcB[(size_t)MAXM * RR];
__device__ float g_dA[MAXM];
__device__ float g_dB[MAXM];
__device__ float g_gi[(size_t)MAXM * 3 * RR];
__device__ float g_gh[(size_t)MAXM * 3 * RR];
__device__ float g_y [(size_t)BB * SS * HH];
// bf16 hi/lo activation pairs
__device__ bf16 g_sxh[(size_t)BB * SS * HH];
__device__ bf16 g_sxl[(size_t)BB * SS * HH];
__device__ bf16 g_xcAh[(size_t)MAXM * HH];
__device__ bf16 g_xcAl[(size_t)MAXM * HH];
__device__ bf16 g_xcBh[(size_t)MAXM * HH];
__device__ bf16 g_xcBl[(size_t)MAXM * HH];
__device__ bf16 g_hcAh[(size_t)MAXM * RR];
__device__ bf16 g_hcAl[(size_t)MAXM * RR];
__device__ bf16 g_hcBh[(size_t)MAXM * RR];
__device__ bf16 g_hcBl[(size_t)MAXM * RR];
__device__ bf16 g_xhh[(size_t)MAXM * (HH + RR)];
__device__ bf16 g_xhl[(size_t)MAXM * (HH + RR)];
__device__ bf16 g_lrh[(size_t)(MAXM/2) * 2 * HH];
__device__ bf16 g_lrl[(size_t)(MAXM/2) * 2 * HH];
// bf16 hi/lo weights
__device__ bf16 g_Whidh[HH * HH];
__device__ bf16 g_Whidl[HH * HH];
__device__ bf16 g_Wbrh[2 * HH * (HH + RR)];
__device__ bf16 g_Wbrl[2 * HH * (HH + RR)];
__device__ bf16 g_Wihh[3 * RR * HH];
__device__ bf16 g_Wihl[3 * RR * HH];
__device__ bf16 g_Whhh[3 * RR * RR];
__device__ bf16 g_Whhl[3 * RR * RR];

// ---------------------------------------------------------------------------
// mma.sync helpers (m16n8k16 bf16, fp32 accumulate)
// ---------------------------------------------------------------------------
__device__ __forceinline__ void ldsm4(uint32_t* r, const void* p) {
    uint32_t a = (uint32_t)__cvta_generic_to_shared(p);
    asm volatile("ldmatrix.sync.aligned.m8n8.x4.shared.b16 {%0,%1,%2,%3}, [%4];"
        : "=r"(r[0]), "=r"(r[1]), "=r"(r[2]), "=r"(r[3]) : "r"(a));
}
__device__ __forceinline__ void mma_bf16(float* d, const uint32_t* a, uint32_t b0, uint32_t b1) {
    asm volatile("mma.sync.aligned.m16n8k16.row.col.f32.bf16.bf16.f32 "
        "{%0,%1,%2,%3}, {%4,%5,%6,%7}, {%8,%9}, {%0,%1,%2,%3};"
        : "+f"(d[0]), "+f"(d[1]), "+f"(d[2]), "+f"(d[3])
        : "r"(a[0]), "r"(a[1]), "r"(a[2]), "r"(a[3]), "r"(b0), "r"(b1));
}

// ---------------------------------------------------------------------------
// HGEMM with bf16x3 split: C[M,N] = epi( (Ah+Al)[M,K] @ (Wh+Wl)[N,K]^T + bias )
// computed as Ah@Wh + Al@Wh + Ah@Wl (3-phase K loop), fp32 accumulate.
//   EPI 0: bias          EPI 1: selu(bias)       EPI 2: P[r>>1] - selu(bias)
//   OF32 -> write Cf (fp32),  OBF -> write Chi/Clo (bf16 hi/lo split)
// Requires N % 128 == 0, K % 32 == 0.
// ---------------------------------------------------------------------------
template<int EPI, bool OF32, bool OBF>
__global__ __launch_bounds__(256, 2)
void hgemm3(const bf16* __restrict__ Ah, const bf16* __restrict__ Al,
            const bf16* __restrict__ Wh, const bf16* __restrict__ Wl,
            const float* __restrict__ bias,
            float* __restrict__ Cf, bf16* __restrict__ Chi, bf16* __restrict__ Clo,
            int M, int N, int K, const float* __restrict__ P)
{
    __shared__ bf16 As[2][128][40];
    __shared__ bf16 Ws[2][128][40];

    const int tid = threadIdx.x;
    const int warp = tid >> 5, lane = tid & 31;
    const int wm = warp >> 2, wn = warp & 3;      // 2 x 4 warp grid
    const int row0 = blockIdx.y * 128, col0 = blockIdx.x * 128;

    const int kt = K >> 5;                         // 32-wide k-tiles per phase
    const int total = 3 * kt;

    float acc[4][4][4];
    #pragma unroll
    for (int a = 0; a < 4; a++)
        #pragma unroll
        for (int b = 0; b < 4; b++)
            #pragma unroll
            for (int c = 0; c < 4; c++) acc[a][b][c] = 0.f;

    uint4 ra[2], rw[2];

    auto loadg = [&](int it) {
        int ph = (it >= 2 * kt) ? 2 : (it >= kt ? 1 : 0);
        int k0 = (it - ph * kt) << 5;
        const bf16* Ap = (ph == 1) ? Al : Ah;
        const bf16* Wp = (ph == 2) ? Wl : Wh;
        #pragma unroll
        for (int i = 0; i < 2; i++) {
            int u = (i << 8) + tid;
            int r = u >> 2, c = (u & 3) << 3;
            int gr = row0 + r;
            ra[i] = (gr < M) ? *(const uint4*)(Ap + (size_t)gr * K + k0 + c)
                             : make_uint4(0u, 0u, 0u, 0u);
            rw[i] = *(const uint4*)(Wp + (size_t)(col0 + r) * K + k0 + c);
        }
    };
    auto sts = [&](int buf) {
        #pragma unroll
        for (int i = 0; i < 2; i++) {
            int u = (i << 8) + tid;
            int r = u >> 2, c = (u & 3) << 3;
            *(uint4*)&As[buf][r][c] = ra[i];
            *(uint4*)&Ws[buf][r][c] = rw[i];
        }
    };

    loadg(0);
    sts(0);
    __syncthreads();

    const int a_r = (lane & 15);
    const int a_c = (lane >> 4) << 3;
    const int b_r = (lane & 7) + ((lane >> 4) << 3);
    const int b_c = ((lane >> 3) & 1) << 3;

    for (int it = 0; it < total; ++it) {
        int cur = it & 1;
        bool more = (it + 1 < total);
        if (more) loadg(it + 1);

        #pragma unroll
        for (int s = 0; s < 2; s++) {
            uint32_t afr[4][4], bfr[2][4];
            #pragma unroll
            for (int mt = 0; mt < 4; mt++)
                ldsm4(afr[mt], &As[cur][wm * 64 + mt * 16 + a_r][s * 16 + a_c]);
            #pragma unroll
            for (int p = 0; p < 2; p++)
                ldsm4(bfr[p], &Ws[cur][wn * 32 + p * 16 + b_r][s * 16 + b_c]);
            #pragma unroll
            for (int mt = 0; mt < 4; mt++)
                #pragma unroll
                for (int nt = 0; nt < 4; nt++)
                    mma_bf16(acc[mt][nt], afr[mt],
                             bfr[nt >> 1][(nt & 1) * 2], bfr[nt >> 1][(nt & 1) * 2 + 1]);
        }

        if (more) sts(cur ^ 1);
        __syncthreads();
    }

    // ---- epilogue ----
    const int g = lane >> 2, t = lane & 3;
    #pragma unroll
    for (int mt = 0; mt < 4; mt++) {
        #pragma unroll
        for (int half = 0; half < 2; half++) {
            int r = row0 + wm * 64 + mt * 16 + g + half * 8;
            if (r >= M) continue;
            #pragma unroll
            for (int nt = 0; nt < 4; nt++) {
                int c = col0 + wn * 32 + nt * 8 + (t << 1);
                float v0 = acc[mt][nt][half * 2 + 0] + bias[c];
                float v1 = acc[mt][nt][half * 2 + 1] + bias[c + 1];
                if (EPI == 1) { v0 = seluf(v0); v1 = seluf(v1); }
                if (EPI == 2) {
                    float2 p = *(const float2*)(P + (size_t)(r >> 1) * HH + c);
                    v0 = p.x - seluf(v0);
                    v1 = p.y - seluf(v1);
                }
                if (OF32) *(float2*)(Cf + (size_t)r * N + c) = make_float2(v0, v1);
                if (OBF) {
                    bf16 h0, l0, h1, l1;
                    split1(v0, h0, l0); split1(v1, h1, l1);
                    *(__nv_bfloat162*)(Chi + (size_t)r * N + c) = __nv_bfloat162(h0, h1);
                    *(__nv_bfloat162*)(Clo + (size_t)r * N + c) = __nv_bfloat162(l0, l1);
                }
            }
        }
    }
}

// ---------------------------------------------------------------------------
// Elementwise kernels
// ---------------------------------------------------------------------------
__global__ void split_kernel(const float* __restrict__ in, bf16* __restrict__ h,
                             bf16* __restrict__ l, int n) {
    int i = blockIdx.x * blockDim.x + threadIdx.x;
    if (i < n) split1(in[i], h[i], l[i]);
}

__global__ void selu_split_kernel(const float* __restrict__ in, bf16* __restrict__ h,
                                  bf16* __restrict__ l, int n) {
    int i = blockIdx.x * blockDim.x + threadIdx.x;
    if (i < n) split1(seluf(in[i]), h[i], l[i]);
}

__global__ void mean_split_kernel(const float* __restrict__ y, float* __restrict__ xc,
                                  bf16* __restrict__ xch, bf16* __restrict__ xcl) {
    int i = blockIdx.x * blockDim.x + threadIdx.x;   // over B*H
    if (i >= BB * HH) return;
    int b = i >> 10, h = i & (HH - 1);
    float s = 0.f;
    #pragma unroll 8
    for (int t = 0; t < SS; t++) s += y[((size_t)(b * SS + t)) * HH + h];
    float v = s * (1.f / SS);
    xc[i] = v;
    split1(v, xch[i], xcl[i]);
}

__global__ void zero32_kernel(uint32_t* p, int n) {
    int i = blockIdx.x * blockDim.x + threadIdx.x;
    if (i < n) p[i] = 0u;
}

__global__ void gru_split_kernel(const float* __restrict__ gi, const float* __restrict__ gh,
                                 float* __restrict__ hc, bf16* __restrict__ hch,
                                 bf16* __restrict__ hcl, int M) {
    int i = blockIdx.x * blockDim.x + threadIdx.x;
    if (i >= M * RR) return;
    int m = i >> 8, j = i & (RR - 1);
    size_t o = (size_t)m * (3 * RR) + j;
    float ir = gi[o], iz = gi[o + RR], inn = gi[o + 2 * RR];
    float hr = gh[o], hz = gh[o + RR], hn  = gh[o + 2 * RR];
    float r = sigmoidf_(ir + hr);
    float z = sigmoidf_(iz + hz);
    float n = tanhf(inn + r * hn);
    size_t ho = (size_t)m * RR + j;
    float v = (1.f - z) * n + z * hc[ho];
    hc[ho] = v;
    split1(v, hch[ho], hcl[ho]);
}

// xh hi/lo = [xc hi/lo | hc hi/lo]   (uint2 = 4 bf16 granularity)
__global__ void concat_bf_kernel(const bf16* __restrict__ xch, const bf16* __restrict__ xcl,
                                 const bf16* __restrict__ hch, const bf16* __restrict__ hcl,
                                 bf16* __restrict__ xhh, bf16* __restrict__ xhl, int M) {
    int i = blockIdx.x * blockDim.x + threadIdx.x;   // over M*320
    if (i >= M * 320) return;
    int m = i / 320, k = i - m * 320;
    uint2 vh, vl;
    if (k < 256) {
        vh = ((const uint2*)xch)[(size_t)m * 256 + k];
        vl = ((const uint2*)xcl)[(size_t)m * 256 + k];
    } else {
        vh = ((const uint2*)hch)[(size_t)m * 64 + (k - 256)];
        vl = ((const uint2*)hcl)[(size_t)m * 64 + (k - 256)];
    }
    ((uint2*)xhh)[(size_t)m * 320 + k] = vh;
    ((uint2*)xhl)[(size_t)m * 320 + k] = vl;
}

// depth += sigmoid([xc|hc] . W_hb + b_hb), straight from fp32 xc/hc (no xh f32)
__global__ void hb_kernel(const float* __restrict__ xc, const float* __restrict__ hc,
                          const float* __restrict__ Whb, const float* __restrict__ bhb,
                          const float* __restrict__ dIn, float* __restrict__ dOut, int M) {
    int w = (blockIdx.x * blockDim.x + threadIdx.x) >> 5;
    int lane = threadIdx.x & 31;
    if (w >= M) return;
    const float4* xr = (const float4*)(xc + (size_t)w * HH);
    const float4* hr = (const float4*)(hc + (size_t)w * RR);
    const float4* w4 = (const float4*)Whb;
    float s = 0.f;
    #pragma unroll 4
    for (int i = lane; i < 256; i += 32) {
        float4 a = xr[i], b = w4[i];
        s += a.x * b.x + a.y * b.y + a.z * b.z + a.w * b.w;
    }
    #pragma unroll 2
    for (int i = lane; i < 64; i += 32) {
        float4 a = hr[i], b = w4[256 + i];
        s += a.x * b.x + a.y * b.y + a.z * b.z + a.w * b.w;
    }
    #pragma unroll
    for (int o = 16; o; o >>= 1) s += __shfl_xor_sync(0xffffffffu, s, o);
    if (lane == 0) dOut[w] = dIn[w] + sigmoidf_(s + bhb[0]);
}

__global__ void repeat_kernel(const float* __restrict__ hcIn, const bf16* __restrict__ hcInH,
                              const bf16* __restrict__ hcInL, const float* __restrict__ dIn,
                              float* __restrict__ hcOut, bf16* __restrict__ hcOutH,
                              bf16* __restrict__ hcOutL, float* __restrict__ dOut, int M2) {
    int i = blockIdx.x * blockDim.x + threadIdx.x;   // over M2*64
    if (i >= M2 * 64) return;
    int m = i >> 6, j = i & 63;
    ((float4*)hcOut)[(size_t)m * 64 + j] = ((const float4*)hcIn)[(size_t)(m >> 1) * 64 + j];
    ((uint2*)hcOutH)[(size_t)m * 64 + j] = ((const uint2*)hcInH)[(size_t)(m >> 1) * 64 + j];
    ((uint2*)hcOutL)[(size_t)m * 64 + j] = ((const uint2*)hcInL)[(size_t)(m >> 1) * 64 + j];
    if (j == 0) dOut[m] = dIn[m >> 1];
}

__global__ void out_kernel(const float* __restrict__ xc, const float* __restrict__ dep,
                           float* __restrict__ out) {
    int i = blockIdx.x * blockDim.x + threadIdx.x;   // over 32768*1025
    if (i >= MAXM * (HH + 1)) return;
    int m = i / (HH + 1), k = i - m * (HH + 1);
    out[i] = (k < HH) ? xc[(size_t)m * HH + k] : dep[m];
}

// ---------------------------------------------------------------------------
// Host driver (graph-capturable: only kernel launches)
// ---------------------------------------------------------------------------
static inline int cdiv(int a, int b) { return (a + b - 1) / b; }

extern "C" void kernel_launch(void* const* d_in, const int* in_sizes, int n_in,
                              void* d_out, int out_size)
{
    const float* x        = (const float*)d_in[0];
    const float* W_hidden = (const float*)d_in[1];
    const float* b_hidden = (const float*)d_in[2];
    const float* W_hb     = (const float*)d_in[3];
    const float* b_hb     = (const float*)d_in[4];
    const float* W_branch = (const float*)d_in[5];
    const float* b_branch = (const float*)d_in[6];
    const float* W_ih     = (const float*)d_in[7];
    const float* W_hh     = (const float*)d_in[8];
    const float* b_ih     = (const float*)d_in[9];
    const float* b_hh     = (const float*)d_in[10];

    float *xcA, *xcB, *hcA, *hcB, *dA, *dB, *gi, *gh, *y;
    bf16 *sxh, *sxl, *xcAh, *xcAl, *xcBh, *xcBl, *hcAh, *hcAl, *hcBh, *hcBl;
    bf16 *xhh, *xhl, *lrh, *lrl;
    bf16 *Whidh, *Whidl, *Wbrh, *Wbrl, *Wihh, *Wihl, *Whhh, *Whhl;

    cudaGetSymbolAddress((void**)&xcA, g_xcA);  cudaGetSymbolAddress((void**)&xcB, g_xcB);
    cudaGetSymbolAddress((void**)&hcA, g_hcA);  cudaGetSymbolAddress((void**)&hcB, g_hcB);
    cudaGetSymbolAddress((void**)&dA,  g_dA);   cudaGetSymbolAddress((void**)&dB,  g_dB);
    cudaGetSymbolAddress((void**)&gi,  g_gi);   cudaGetSymbolAddress((void**)&gh,  g_gh);
    cudaGetSymbolAddress((void**)&y,   g_y);
    cudaGetSymbolAddress((void**)&sxh, g_sxh);  cudaGetSymbolAddress((void**)&sxl, g_sxl);
    cudaGetSymbolAddress((void**)&xcAh, g_xcAh); cudaGetSymbolAddress((void**)&xcAl, g_xcAl);
    cudaGetSymbolAddress((void**)&xcBh, g_xcBh); cudaGetSymbolAddress((void**)&xcBl, g_xcBl);
    cudaGetSymbolAddress((void**)&hcAh, g_hcAh); cudaGetSymbolAddress((void**)&hcAl, g_hcAl);
    cudaGetSymbolAddress((void**)&hcBh, g_hcBh); cudaGetSymbolAddress((void**)&hcBl, g_hcBl);
    cudaGetSymbolAddress((void**)&xhh, g_xhh);  cudaGetSymbolAddress((void**)&xhl, g_xhl);
    cudaGetSymbolAddress((void**)&lrh, g_lrh);  cudaGetSymbolAddress((void**)&lrl, g_lrl);
    cudaGetSymbolAddress((void**)&Whidh, g_Whidh); cudaGetSymbolAddress((void**)&Whidl, g_Whidl);
    cudaGetSymbolAddress((void**)&Wbrh, g_Wbrh);   cudaGetSymbolAddress((void**)&Wbrl, g_Wbrl);
    cudaGetSymbolAddress((void**)&Wihh, g_Wihh);   cudaGetSymbolAddress((void**)&Wihl, g_Wihl);
    cudaGetSymbolAddress((void**)&Whhh, g_Whhh);   cudaGetSymbolAddress((void**)&Whhl, g_Whhl);

    const int nsx = BB * SS * HH;  // 2,097,152

    // ---- weight splits (cheap; captured into the graph) ----
    split_kernel<<<cdiv(HH*HH, 256), 256>>>(W_hidden, Whidh, Whidl, HH*HH);
    split_kernel<<<cdiv(2*HH*(HH+RR), 256), 256>>>(W_branch, Wbrh, Wbrl, 2*HH*(HH+RR));
    split_kernel<<<cdiv(3*RR*HH, 256), 256>>>(W_ih, Wihh, Wihl, 3*RR*HH);
    split_kernel<<<cdiv(3*RR*RR, 256), 256>>>(W_hh, Whhh, Whhl, 3*RR*RR);

    // ---- root: xc0 = mean_s selu(selu(x) @ W_hidden^T + b_hidden) ----
    selu_split_kernel<<<cdiv(nsx, 256), 256>>>(x, sxh, sxl, nsx);
    hgemm3<1, true, false><<<dim3(HH/128, (BB*SS)/128), 256>>>(
        sxh, sxl, Whidh, Whidl, b_hidden, y, nullptr, nullptr, BB*SS, HH, HH, nullptr);
    mean_split_kernel<<<cdiv(BB*HH, 256), 256>>>(y, xcA, xcAh, xcAl);

    // zero GRU state (fp32 + bf16 pairs) and depth
    zero32_kernel<<<cdiv(BB*RR, 256), 256>>>((uint32_t*)hcA, BB*RR);
    zero32_kernel<<<cdiv(BB*RR/2, 256), 256>>>((uint32_t*)hcAh, BB*RR/2);
    zero32_kernel<<<cdiv(BB*RR/2, 256), 256>>>((uint32_t*)hcAl, BB*RR/2);
    zero32_kernel<<<1, 64>>>((uint32_t*)dA, BB);

    // ---- levels 0 .. DEPTH-1 ----
    for (int d = 0; d < DEPTH; d++) {
        int M  = BB << d;
        int M2 = M << 1;
        int gy = cdiv(M, 128);

        hgemm3<0, true, false><<<dim3(768/128, gy), 256>>>(
            xcAh, xcAl, Wihh, Wihl, b_ih, gi, nullptr, nullptr, M, 768, HH, nullptr);
        hgemm3<0, true, false><<<dim3(768/128, gy), 256>>>(
            hcAh, hcAl, Whhh, Whhl, b_hh, gh, nullptr, nullptr, M, 768, RR, nullptr);
        gru_split_kernel<<<cdiv(M*RR, 256), 256>>>(gi, gh, hcA, hcAh, hcAl, M);

        hb_kernel<<<cdiv(M*32, 256), 256>>>(xcA, hcA, W_hb, b_hb, dA, dA, M);
        concat_bf_kernel<<<cdiv(M*320, 256), 256>>>(xcAh, xcAl, hcAh, hcAl, xhh, xhl, M);

        hgemm3<1, false, true><<<dim3(2*HH/128, gy), 256>>>(
            xhh, xhl, Wbrh, Wbrl, b_branch, nullptr, lrh, lrl, M, 2*HH, HH+RR, nullptr);

        hgemm3<2, true, true><<<dim3(HH/128, cdiv(M2, 128)), 256>>>(
            lrh, lrl, Whidh, Whidl, b_hidden, xcB, xcBh, xcBl, M2, HH, HH, xcA);

        repeat_kernel<<<cdiv(M2*64, 256), 256>>>(hcA, hcAh, hcAl, dA,
                                                 hcB, hcBh, hcBl, dB, M2);

        float* t;  bf16* bt;
        t = xcA; xcA = xcB; xcB = t;
        t = hcA; hcA = hcB; hcB = t;
        t = dA;  dA  = dB;  dB  = t;
        bt = xcAh; xcAh = xcBh; xcBh = bt;
        bt = xcAl; xcAl = xcBl; xcBl = bt;
        bt = hcAh; hcAh = hcBh; hcBh = bt;
        bt = hcAl; hcAl = hcBl; hcBl = bt;
    }

    // ---- leaf step (M = 32768) ----
    {
        int M = MAXM;
        int gy = M / 128;
        hgemm3<0, true, false><<<dim3(768/128, gy), 256>>>(
            xcAh, xcAl, Wihh, Wihl, b_ih, gi, nullptr, nullptr, M, 768, HH, nullptr);
        hgemm3<0, true, false><<<dim3(768/128, gy), 256>>>(
            hcAh, hcAl, Whhh, Whhl, b_hh, gh, nullptr, nullptr, M, 768, RR, nullptr);
        gru_split_kernel<<<cdiv(M*RR, 256), 256>>>(gi, gh, hcA, hcAh, hcAl, M);
        hb_kernel<<<cdiv(M*32, 256), 256>>>(xcA, hcA, W_hb, b_hb, dA, dA, M);
        out_kernel<<<cdiv(M*(HH+1), 256), 256>>>(xcA, dA, (float*)d_out);
    }
}